// round 4
// baseline (speedup 1.0000x reference)
#include <cuda_runtime.h>
#include <cstdint>

// BATCH=16384, NCONDS=50, EMB=64, table rows=100002
// d_in[0]: int32 input [B,51]   d_in[1]: float table [100002,64]
// out: float [B, 64 + 50*64]

constexpr int EMB     = 64;
constexpr int NCONDS  = 50;
constexpr int ROW_IN  = 1 + NCONDS;           // 51
constexpr int ROW_OUT = EMB + NCONDS * EMB;   // 3264

__global__ __launch_bounds__(256) void cond_filter_kernel(
    const int*   __restrict__ inp,
    const float* __restrict__ table,
    float*       __restrict__ out,
    int batch)
{
    const int warp = (blockIdx.x * blockDim.x + threadIdx.x) >> 5;
    const int lane = threadIdx.x & 31;
    if (warp >= batch) return;

    const int g  = lane >> 3;   // group 0..3: which condition of the quad
    const int gl = lane & 7;    // lane within group: float slot [gl*8, gl*8+8)

    const int* row  = inp + (long)warp * ROW_IN;
    float*     orow = out + (long)warp * ROW_OUT;

    // ---- event embedding: each lane holds 8 floats (2x float4) ----
    const int e = __ldg(row);
    const float* erow = table + (long)e * EMB + 8 * gl;
    const float4 ev0 = *reinterpret_cast<const float4*>(erow);
    const float4 ev1 = *reinterpret_cast<const float4*>(erow + 4);

    if (g == 0) {  // group 0 writes the un-normalized event embedding (streaming)
        __stcs(reinterpret_cast<float4*>(orow + 8 * gl),     ev0);
        __stcs(reinterpret_cast<float4*>(orow + 8 * gl + 4), ev1);
    }

    float ss = ev0.x*ev0.x + ev0.y*ev0.y + ev0.z*ev0.z + ev0.w*ev0.w
             + ev1.x*ev1.x + ev1.y*ev1.y + ev1.z*ev1.z + ev1.w*ev1.w;
    #pragma unroll
    for (int o = 4; o; o >>= 1) ss += __shfl_xor_sync(0xffffffffu, ss, o);
    const float rinv = rsqrtf(ss);
    float en[8];
    en[0]=ev0.x*rinv; en[1]=ev0.y*rinv; en[2]=ev0.z*rinv; en[3]=ev0.w*rinv;
    en[4]=ev1.x*rinv; en[5]=ev1.y*rinv; en[6]=ev1.z*rinv; en[7]=ev1.w*rinv;

    // ---- conditions, 4 per iteration (one per 8-lane group) ----
    // filtered_c = cond * dot(event_nrm, cond) / dot(cond, cond)
    int cidx = min(g, NCONDS - 1);
    int ci = __ldg(row + 1 + cidx);
    const float* crow = table + (long)ci * EMB + 8 * gl;
    float4 cv0 = *reinterpret_cast<const float4*>(crow);
    float4 cv1 = *reinterpret_cast<const float4*>(crow + 4);

    float* obase = orow + EMB + 8 * gl;

    #pragma unroll 1
    for (int c = 0; c < NCONDS; c += 4) {
        const float4 a0 = cv0, a1 = cv1;
        const int my = cidx;            // this group's condition index (clamped)

        if (c + 4 < NCONDS) {           // prefetch next quad
            cidx = min(c + 4 + g, NCONDS - 1);
            ci = __ldg(row + 1 + cidx);
            const float* p = table + (long)ci * EMB + 8 * gl;
            cv0 = *reinterpret_cast<const float4*>(p);
            cv1 = *reinterpret_cast<const float4*>(p + 4);
        }

        float dec = en[0]*a0.x + en[1]*a0.y + en[2]*a0.z + en[3]*a0.w
                  + en[4]*a1.x + en[5]*a1.y + en[6]*a1.z + en[7]*a1.w;
        float dcc = a0.x*a0.x + a0.y*a0.y + a0.z*a0.z + a0.w*a0.w
                  + a1.x*a1.x + a1.y*a1.y + a1.z*a1.z + a1.w*a1.w;
        #pragma unroll
        for (int o = 4; o; o >>= 1) {   // reduce within each 8-lane group
            dec += __shfl_xor_sync(0xffffffffu, dec, o);
            dcc += __shfl_xor_sync(0xffffffffu, dcc, o);
        }

        const float s = dec / dcc;
        float4 w0, w1;
        w0.x = a0.x*s; w0.y = a0.y*s; w0.z = a0.z*s; w0.w = a0.w*s;
        w1.x = a1.x*s; w1.y = a1.y*s; w1.z = a1.z*s; w1.w = a1.w*s;
        float* o8 = obase + (long)my * EMB;   // clamped groups rewrite cond 49 (same data)
        __stcs(reinterpret_cast<float4*>(o8),     w0);
        __stcs(reinterpret_cast<float4*>(o8 + 4), w1);
    }
}

extern "C" void kernel_launch(void* const* d_in, const int* in_sizes, int n_in,
                              void* d_out, int out_size)
{
    const int*   inp   = (const int*)d_in[0];
    const float* table = (const float*)d_in[1];
    float*       out   = (float*)d_out;

    const int batch = in_sizes[0] / ROW_IN;

    const int threads = 256;                  // 8 warps/block, 1 warp/row
    const int blocks  = (batch + 7) / 8;

    cond_filter_kernel<<<blocks, threads>>>(inp, table, out, batch);
}

// round 7
// speedup vs baseline: 1.2414x; 1.2414x over previous
#include <cuda_runtime.h>
#include <cstdint>

// BATCH=16384, NCONDS=50, EMB=64, table rows=100002
// d_in[0]: int32 input [B,51]   d_in[1]: float table [100002,64]
// out: float [B, 64 + 50*64]

constexpr int EMB     = 64;
constexpr int NCONDS  = 50;
constexpr int ROW_IN  = 1 + NCONDS;           // 51
constexpr int ROW_OUT = EMB + NCONDS * EMB;   // 3264

__global__ __launch_bounds__(256, 8) void cond_filter_kernel(
    const int*   __restrict__ inp,
    const float* __restrict__ table,
    float*       __restrict__ out,
    int batch)
{
    const unsigned FULL = 0xffffffffu;
    const int warp = (blockIdx.x * blockDim.x + threadIdx.x) >> 5;
    const int lane = threadIdx.x & 31;
    if (warp >= batch) return;

    const int half = lane >> 4;     // 0: even conds, 1: odd conds
    const int hl   = lane & 15;     // lane within 16-lane group (float4 slot)

    const int* row  = inp + (long)warp * ROW_IN;
    float*     orow = out + (long)warp * ROW_OUT;

    // ---- event embedding (both halves load; event_nrm needed in all lanes) ----
    const int e = __ldg(row);
    const float4 ev = *reinterpret_cast<const float4*>(table + (long)e * EMB + 4 * hl);

    if (half == 0)  // write un-normalized event embedding (streaming: no reuse)
        __stcs(reinterpret_cast<float4*>(orow + 4 * hl), ev);

    // IMPORTANT: reduce within the 16-lane half only (offsets 8..1).
    // Both halves hold the same 64 floats; offset 16 would double-count.
    float ss = ev.x * ev.x + ev.y * ev.y + ev.z * ev.z + ev.w * ev.w;
    #pragma unroll
    for (int o = 8; o; o >>= 1) ss += __shfl_xor_sync(FULL, ss, o);
    const float rinv = rsqrtf(ss);
    const float enx = ev.x * rinv, eny = ev.y * rinv;
    const float enz = ev.z * rinv, enw = ev.w * rinv;

    // ---- conditions, 2 per iteration (one per 16-lane half) ----
    // filtered_c = cond * dot(event_nrm, cond) / dot(cond, cond)
    int    ci = __ldg(row + 1 + half);
    float4 cv = *reinterpret_cast<const float4*>(table + (long)ci * EMB + 4 * hl);

    float* ocond = orow + EMB + (long)half * EMB + 4 * hl;
    const bool evenl = (lane & 1) == 0;

    #pragma unroll 1
    for (int c = 0; c < NCONDS; c += 2) {
        const float4 a = cv;
        if (c + 2 < NCONDS) {  // prefetch next pair
            ci = __ldg(row + 3 + c + half);
            cv = *reinterpret_cast<const float4*>(table + (long)ci * EMB + 4 * hl);
        }

        // per-lane partials
        float p = enx * a.x + eny * a.y + enz * a.z + enw * a.w;   // dot(e_n, c)
        float q = a.x * a.x + a.y * a.y + a.z * a.z + a.w * a.w;   // dot(c, c)

        // packed dual reduction over 16-lane group: 5 shfls instead of 8.
        // Even lanes carry the p-sum, odd lanes the q-sum, then redistribute.
        float x = evenl ? p : q;
        float y = evenl ? q : p;
        x += __shfl_xor_sync(FULL, y, 1);   // even: p_l + p_{l^1}; odd: q_l + q_{l^1}
        x += __shfl_xor_sync(FULL, x, 2);
        x += __shfl_xor_sync(FULL, x, 4);
        x += __shfl_xor_sync(FULL, x, 8);
        const float t = __shfl_xor_sync(FULL, x, 1);
        const float dec = evenl ? x : t;
        const float dcc = evenl ? t : x;

        const float s = __fdividef(dec, dcc);
        float4 w;
        w.x = a.x * s; w.y = a.y * s; w.z = a.z * s; w.w = a.w * s;
        __stcs(reinterpret_cast<float4*>(ocond + (long)c * EMB), w);
    }
}

extern "C" void kernel_launch(void* const* d_in, const int* in_sizes, int n_in,
                              void* d_out, int out_size)
{
    const int*   inp   = (const int*)d_in[0];
    const float* table = (const float*)d_in[1];
    float*       out   = (float*)d_out;

    const int batch = in_sizes[0] / ROW_IN;

    const int threads = 256;                  // 8 warps/block, 1 warp/row
    const int blocks  = (batch + 7) / 8;

    cond_filter_kernel<<<blocks, threads>>>(inp, table, out, batch);
}